// round 17
// baseline (speedup 1.0000x reference)
#include <cuda_runtime.h>

#define HW       64
#define NPIX     4096
#define NTASK    24
#define BT       1024
#define IPT      4
#define EDGE_CAP 12288
#define KMAX     (EDGE_CAP / BT)
#define FULL     0xFFFFFFFFu
#define FULL64   0xFFFFFFFFFFFFFFFFull

struct TaskRes { double s2; float pmax; float vfirst; int has; };
__device__ TaskRes g_res[NTASK];
__device__ unsigned g_ctr = 0;   // self-resetting completion counter

struct Shm {
    unsigned           key[NPIX];       // 30-bit monotone order key by pixel
    unsigned short     F[NPIX];         // basin root (local min) by pixel
    float              val[NPIX];       // filtration value (negated for variant 1)
    unsigned short     mpar[NPIX];      // minima union-find parent
    unsigned long long claimY[NPIX];    // 64-bit young-root claims
    unsigned long long claimE[NPIX];    // 64-bit elder-role claims
    unsigned           edges_ab[EDGE_CAP];  // (a<<12)|b
    unsigned short     edges_pj[EDGE_CAP];  // (p<<3)|j  (saddle pixel + slot)
    double             rS2[32];
    float              rPM[32];
    float              rVF[32];
    int                rHas[32];
    int                ne;
};

__device__ __forceinline__ int phfind(unsigned short* par, int a) {
    int p = par[a];
    while (p != a) {                       // path halving (benign races)
        int g = par[p];
        par[a] = (unsigned short)g;
        a = g; p = par[a];
    }
    return a;
}

__global__ __launch_bounds__(BT) void uf_kernel(const float* __restrict__ x,
                                                float* __restrict__ out)
{
    extern __shared__ char raw[];
    Shm& sh = *(Shm*)raw;

    const int task    = blockIdx.x;
    const int img     = task >> 1;
    const int variant = task & 1;          // 0: sublevel v (8-conn); 1: sublevel -v (4-conn)
    const int b       = img / 3;
    const int c       = img % 3 + 1;
    const float* v    = x + (size_t)(b * 4 + c) * NPIX;
    const int tid     = threadIdx.x;
    const int lane    = tid & 31, warp = tid >> 5;
    const int nOff    = variant ? 4 : 8;

    const int drs[8] = {-1, 1, 0, 0, -1, -1, 1, 1};
    const int dcs[8] = { 0, 0,-1, 1, -1,  1,-1, 1};

    // ---- phase A: load; key/val/mpar/claims ---------------------------------
    if (tid == 0) sh.ne = 0;
    float4 vin = ((const float4*)v)[tid];      // p = tid*4 .. tid*4+3
    float vloc[IPT] = {vin.x, vin.y, vin.z, vin.w};
    float vmin = 1e30f;
#pragma unroll
    for (int i = 0; i < IPT; i++) {
        int p = tid * IPT + i;
        float val = vloc[i];
        unsigned bits = __float_as_uint(val);                // monotone for v >= 0
        sh.key[p] = (variant ? ~bits : bits) & 0x3FFFFFFFu;  // total order (asc)
        float sv = variant ? -val : val;
        sh.val[p]    = sv;
        if (sv < vmin) vmin = sv;      // first-in-order pixel's value (ties equal)
        sh.mpar[p]   = (unsigned short)p;
        sh.claimY[p] = FULL64;
        sh.claimE[p] = FULL64;
    }
    __syncthreads();

    // ---- phase B: steepest descent by 42-bit key (key30<<12 | idx) ---------
#pragma unroll
    for (int i = 0; i < IPT; i++) {
        int p = tid * IPT + i;
        int r = p >> 6, cc = p & 63;
        int best = p;
        unsigned long long bk = ((unsigned long long)sh.key[p] << 12) | p;
        for (int k = 0; k < nOff; k++) {
            int rr = r + drs[k], c2 = cc + dcs[k];
            if (rr >= 0 && rr < HW && c2 >= 0 && c2 < HW) {
                int q = rr * HW + c2;
                unsigned long long kq =
                    ((unsigned long long)sh.key[q] << 12) | q;
                if (kq < bk) { bk = kq; best = q; }
            }
        }
        sh.F[p] = (unsigned short)best;
    }
    __syncthreads();

    // ---- phase C: pointer jumping until converged (benign races) -----------
    int changed = 1;
    while (__syncthreads_or(changed)) {
        changed = 0;
#pragma unroll
        for (int i = 0; i < IPT; i++) {
            int p = tid * IPT + i;
            int f = sh.F[p];
            int g = sh.F[f];
            if (g != f) { sh.F[p] = (unsigned short)g; changed = 1; }
        }
    }

    // ---- phase D: edge emission (per-thread atomic slot alloc) -------------
#pragma unroll
    for (int i = 0; i < IPT; i++) {
        int p = tid * IPT + i;
        unsigned long long kp = ((unsigned long long)sh.key[p] << 12) | p;
        int r = p >> 6, cc = p & 63;
        unsigned short fs[8]; int nf = 0;
        for (int k = 0; k < nOff; k++) {
            int rr = r + drs[k], c2 = cc + dcs[k];
            if (rr >= 0 && rr < HW && c2 >= 0 && c2 < HW) {
                int q = rr * HW + c2;
                unsigned long long kq =
                    ((unsigned long long)sh.key[q] << 12) | q;
                if (kq < kp) {                     // strictly lower neighbor
                    unsigned short f = sh.F[q];
                    bool dup = false;
                    for (int j = 0; j < nf; j++) if (fs[j] == f) dup = true;
                    if (!dup) fs[nf++] = f;
                }
            }
        }
        if (nf >= 2) {
            int base = atomicAdd(&sh.ne, nf - 1);
            unsigned ab0 = (unsigned)fs[0] << 12;
            for (int j = 1; j < nf; j++) {
                int slot = base + j - 1;
                if (slot < EDGE_CAP) {
                    sh.edges_ab[slot] = ab0 | fs[j];
                    sh.edges_pj[slot] = (unsigned short)((p << 3) | j);
                }
            }
        }
    }
    __syncthreads();

    // ---- phase E: block-wide parallel Kruskal (64-bit exact-order claims) --
    {
        unsigned short*       mpar   = sh.mpar;
        unsigned long long*   claimY = sh.claimY;
        unsigned long long*   claimE = sh.claimE;
        const int ne = sh.ne < EDGE_CAP ? sh.ne : EDGE_CAP;

        double S2 = 0.0; float pmax = 0.f; int has = 0;

        unsigned actmask = 0;
        unsigned short ya[KMAX], ea[KMAX], pj[KMAX];
        float          va[KMAX];
#pragma unroll
        for (int k = 0; k < KMAX; k++) {
            int slot = tid + k * BT;
            if (slot < ne) {
                unsigned ab = sh.edges_ab[slot];
                ya[k] = (unsigned short)(ab >> 12);
                ea[k] = (unsigned short)(ab & 0xFFFu);
                pj[k] = sh.edges_pj[slot];
                va[k] = sh.val[pj[k] >> 3];
                actmask |= 1u << k;
            }
        }

        // claim token: prefix16<<45 | key30<<15 | p<<3 | j  (exact total order,
        // descending prefix per round -> stale claims auto-expire, no reset)
        unsigned long long prefix = 0xFFFFull << 45;
        int any = __syncthreads_or(actmask != 0);
        while (any) {
            unsigned claimed = 0;
            // phase 1: short finds from cached roots, post claims
#pragma unroll
            for (int k = 0; k < KMAX; k++) if (actmask & (1u << k)) {
                int fa = phfind(mpar, ya[k]);      // 0-2 hops after round 1
                int fb = phfind(mpar, ea[k]);
                if (fa == fb) { actmask &= ~(1u << k); continue; }
                // elder rule by 42-bit key (same order as rank)
                unsigned long long ka = ((unsigned long long)sh.key[fa] << 12) | fa;
                unsigned long long kb = ((unsigned long long)sh.key[fb] << 12) | fb;
                int eld, yng;
                if (ka < kb) { eld = fa; yng = fb; }
                else         { eld = fb; yng = fa; }
                ya[k] = (unsigned short)yng;       // refresh cache
                ea[k] = (unsigned short)eld;
                unsigned long long kk = prefix
                    | ((unsigned long long)sh.key[pj[k] >> 3] << 15)
                    | pj[k];
                atomicMin(&claimY[yng], kk);       // I want to merge yng away
                atomicMin(&claimE[eld], kk);       // I currently see eld as elder
                claimed |= 1u << k;
            }
            __syncthreads();
            // phase 2: commit iff (1) min young-claim of y is me (this round)
            //                     (2) no current-round edge has y as elder
#pragma unroll
            for (int k = 0; k < KMAX; k++) if (claimed & (1u << k)) {
                unsigned long long kk = prefix
                    | ((unsigned long long)sh.key[pj[k] >> 3] << 15)
                    | pj[k];
                int yng = ya[k];
                if (claimY[yng] == kk && claimE[yng] > kk) {
                    float p = va[k] - sh.val[yng]; // birth = young root's value
                    if (p > 0.f) {
                        S2 += (double)p * (double)p;
                        if (p > pmax) pmax = p;
                        has = 1;
                    }
                    mpar[yng] = ea[k];
                    actmask &= ~(1u << k);
                }
            }
            prefix -= 1ull << 45;            // stale claims auto-expire
            any = __syncthreads_or(actmask != 0);
        }

        // block reduction (S2 / pmax / has / vfirst)
#pragma unroll
        for (int off = 16; off; off >>= 1) {
            S2 += __shfl_down_sync(FULL, S2, off);
            float pm = __shfl_down_sync(FULL, pmax, off);
            pmax = fmaxf(pmax, pm);
            has |= __shfl_down_sync(FULL, has, off);
            float vm = __shfl_down_sync(FULL, vmin, off);
            vmin = fminf(vmin, vm);
        }
        if (lane == 0) {
            sh.rS2[warp] = S2; sh.rPM[warp] = pmax;
            sh.rHas[warp] = has; sh.rVF[warp] = vmin;
        }
        __syncthreads();

        if (tid == 0) {
            double tS2 = 0.0; float tPM = 0.f; int tH = 0; float tVF = 1e30f;
            for (int w = 0; w < 32; w++) {
                tS2 += sh.rS2[w];
                tPM  = fmaxf(tPM, sh.rPM[w]);
                tH  |= sh.rHas[w];
                tVF  = fminf(tVF, sh.rVF[w]);
            }
            TaskRes r;
            r.s2 = tS2; r.pmax = tPM; r.has = tH;
            r.vfirst = tVF;                       // essential birth (global min val)
            g_res[task] = r;
            __threadfence();
            unsigned old = atomicAdd(&g_ctr, 1u);
            if (old == NTASK - 1) {               // last block: compute the loss
                __threadfence();
                volatile TaskRes* gr = g_res;
                const int nfx[3] = {0, 0, 1};
                const int nf1[3] = {0, 1, 0};
                double loss = 0.0;
                for (int im = 0; im < 12; im++) {
                    int ci = im % 3;
                    double s2a = gr[im*2].s2;   float pma = gr[im*2].pmax;
                    int    ha  = gr[im*2].has;  float vf  = gr[im*2].vfirst;
                    double s2b = gr[im*2+1].s2; float pmb = gr[im*2+1].pmax;
                    int    hb  = gr[im*2+1].has;
                    double h0 = (double)vf * (double)vf + s2a;
                    if (nfx[ci]) {
                        if (ha) { double p = pma; h0 += (1.0-p)*(1.0-p) - p*p; }
                        else     h0 += 1.0;
                    }
                    double h1 = s2b;
                    if (nf1[ci]) {
                        if (hb) { double p = pmb; h1 += (1.0-p)*(1.0-p) - p*p; }
                        else     h1 += 1.0;
                    }
                    loss += h0 + h1;
                }
                out[0] = (float)(loss * 0.25);
                atomicSub(&g_ctr, (unsigned)NTASK);   // reset for next launch
            }
        }
    }
}

extern "C" void kernel_launch(void* const* d_in, const int* in_sizes, int n_in,
                              void* d_out, int out_size)
{
    (void)in_sizes; (void)n_in; (void)out_size;
    const float* x = (const float*)d_in[0];
    cudaFuncSetAttribute(uf_kernel, cudaFuncAttributeMaxDynamicSharedMemorySize,
                         (int)sizeof(Shm));
    uf_kernel<<<NTASK, BT, sizeof(Shm)>>>(x, (float*)d_out);
}